// round 2
// baseline (speedup 1.0000x reference)
#include <cuda_runtime.h>

#define NMAX 100000

// N-sized scratch (all __device__ globals; no allocation anywhere)
__device__ float  g_deg [NMAX];
__device__ float  g_dis [NMAX];
__device__ float4 g_y   [NMAX * 4];   // dis[n] * (lin_node output), layer 1 then reused for layer 2
__device__ float4 g_A1  [NMAX * 4];   // x1 @ w_e1[0:16]
__device__ float4 g_B1  [NMAX * 4];   // x1 @ w_e1[19:35]
__device__ float4 g_A2  [NMAX * 4];   // x2 @ w_e2[0:16]
__device__ float4 g_B2  [NMAX * 4];   // x2 @ w_e2[32:48]
__device__ float  g_agg1[NMAX * 16];
__device__ float  g_agg2[NMAX * 16];

__device__ __forceinline__ float relu(float v) { return fmaxf(v, 0.0f); }

// ---------------------------------------------------------------- degree
__global__ void k_deg(const int* __restrict__ ei, int E) {
    int e = blockIdx.x * blockDim.x + threadIdx.x;
    if (e < E) atomicAdd(&g_deg[ei[(size_t)E + e]], 1.0f);
}

// ------------------------------------------------- node precompute layer 1
__global__ void k_node1(const float* __restrict__ x,
                        const float* __restrict__ wn1, const float* __restrict__ bn1,
                        const float* __restrict__ we1, int N) {
    __shared__ float swn[48], sbn[16], sA[256], sB[256];
    for (int i = threadIdx.x; i < 48; i += blockDim.x) swn[i] = wn1[i];
    for (int i = threadIdx.x; i < 16; i += blockDim.x) sbn[i] = bn1[i];
    for (int i = threadIdx.x; i < 256; i += blockDim.x) {
        sA[i] = we1[i];            // rows 0..15  (x_src part)
        sB[i] = we1[304 + i];      // rows 19..34 (x_dst part)
    }
    __syncthreads();
    int n = blockIdx.x * blockDim.x + threadIdx.x;
    if (n >= N) return;

    float x0 = x[(size_t)n*3], x1 = x[(size_t)n*3+1], x2 = x[(size_t)n*3+2];
    float dis = rsqrtf(g_deg[n]);
    g_dis[n] = dis;

    float h[16];
#pragma unroll
    for (int k = 0; k < 16; k++)
        h[k] = sbn[k] + x0*swn[k] + x1*swn[16+k] + x2*swn[32+k];

    float4* Y = &g_y[(size_t)n*4];
#pragma unroll
    for (int q = 0; q < 4; q++)
        Y[q] = make_float4(dis*h[4*q], dis*h[4*q+1], dis*h[4*q+2], dis*h[4*q+3]);

    float a[16], b[16];
#pragma unroll
    for (int k = 0; k < 16; k++) { a[k] = 0.f; b[k] = 0.f; }
#pragma unroll
    for (int j = 0; j < 16; j++)
#pragma unroll
        for (int k = 0; k < 16; k++) {
            a[k] += h[j] * sA[j*16+k];
            b[k] += h[j] * sB[j*16+k];
        }
    float4* A = &g_A1[(size_t)n*4];
    float4* B = &g_B1[(size_t)n*4];
#pragma unroll
    for (int q = 0; q < 4; q++) {
        A[q] = make_float4(a[4*q], a[4*q+1], a[4*q+2], a[4*q+3]);
        B[q] = make_float4(b[4*q], b[4*q+1], b[4*q+2], b[4*q+3]);
    }
}

// ----------------------------------------------------- layer-1 aggregation
__global__ void k_agg(const int* __restrict__ ei, int E, float* __restrict__ agg) {
    int e = blockIdx.x * blockDim.x + threadIdx.x;
    if (e >= E) return;
    int src = ei[e];
    int dst = ei[(size_t)E + e];
    const float4* Y = &g_y[(size_t)src*4];
    float4 y0 = Y[0], y1 = Y[1], y2 = Y[2], y3 = Y[3];
    float* a = agg + (size_t)dst * 16;
    atomicAdd(a+ 0, y0.x); atomicAdd(a+ 1, y0.y); atomicAdd(a+ 2, y0.z); atomicAdd(a+ 3, y0.w);
    atomicAdd(a+ 4, y1.x); atomicAdd(a+ 5, y1.y); atomicAdd(a+ 6, y1.z); atomicAdd(a+ 7, y1.w);
    atomicAdd(a+ 8, y2.x); atomicAdd(a+ 9, y2.y); atomicAdd(a+10, y2.z); atomicAdd(a+11, y2.w);
    atomicAdd(a+12, y3.x); atomicAdd(a+13, y3.y); atomicAdd(a+14, y3.z); atomicAdd(a+15, y3.w);
}

// ------------------------------------------------- node precompute layer 2
__global__ void k_node2(const float* __restrict__ wn2, const float* __restrict__ bn2,
                        const float* __restrict__ we2, int N) {
    __shared__ float sw[256], sbn[16], sA[256], sB[256];
    for (int i = threadIdx.x; i < 16; i += blockDim.x) sbn[i] = bn2[i];
    for (int i = threadIdx.x; i < 256; i += blockDim.x) {
        sw[i] = wn2[i];
        sA[i] = we2[i];            // rows 0..15
        sB[i] = we2[512 + i];      // rows 32..47
    }
    __syncthreads();
    int n = blockIdx.x * blockDim.x + threadIdx.x;
    if (n >= N) return;

    float dis = g_dis[n];
    const float* agg = g_agg1 + (size_t)n * 16;
    float h[16];
#pragma unroll
    for (int k = 0; k < 16; k++) h[k] = relu(dis * agg[k]);

    float v[16];
#pragma unroll
    for (int k = 0; k < 16; k++) v[k] = sbn[k];
#pragma unroll
    for (int j = 0; j < 16; j++)
#pragma unroll
        for (int k = 0; k < 16; k++) v[k] += h[j] * sw[j*16+k];

    float4* Y = &g_y[(size_t)n*4];
#pragma unroll
    for (int q = 0; q < 4; q++)
        Y[q] = make_float4(dis*v[4*q], dis*v[4*q+1], dis*v[4*q+2], dis*v[4*q+3]);

    float a[16], b[16];
#pragma unroll
    for (int k = 0; k < 16; k++) { a[k] = 0.f; b[k] = 0.f; }
#pragma unroll
    for (int j = 0; j < 16; j++)
#pragma unroll
        for (int k = 0; k < 16; k++) {
            a[k] += v[j] * sA[j*16+k];
            b[k] += v[j] * sB[j*16+k];
        }
    float4* A = &g_A2[(size_t)n*4];
    float4* B = &g_B2[(size_t)n*4];
#pragma unroll
    for (int q = 0; q < 4; q++) {
        A[q] = make_float4(a[4*q], a[4*q+1], a[4*q+2], a[4*q+3]);
        B[q] = make_float4(b[4*q], b[4*q+1], b[4*q+2], b[4*q+3]);
    }
}

// ------- layer-2 edge kernel: recompute e1, compute e2, edge MLP, agg2
__global__ void k_edge2(const int* __restrict__ ei, const float* __restrict__ ea,
                        const float* __restrict__ we1, const float* __restrict__ be1,
                        const float* __restrict__ we2, const float* __restrict__ be2,
                        const float* __restrict__ wen1, const float* __restrict__ ben1,
                        const float* __restrict__ wen2, const float* __restrict__ ben2,
                        float* __restrict__ out_edge, float* __restrict__ agg2, int E) {
    __shared__ float sm1[48], sbe1[16], sm2[256], sbe2[16], sw1[256], sb1[16], sw2[48], sb2[3];
    for (int i = threadIdx.x; i < 48; i += blockDim.x) {
        sm1[i] = we1[256 + i];     // w_e1 rows 16..18 (edge_attr part)
        sw2[i] = wen2[i];
    }
    for (int i = threadIdx.x; i < 256; i += blockDim.x) {
        sm2[i] = we2[256 + i];     // w_e2 rows 16..31 (edge part)
        sw1[i] = wen1[i];
    }
    for (int i = threadIdx.x; i < 16; i += blockDim.x) {
        sbe1[i] = be1[i]; sbe2[i] = be2[i]; sb1[i] = ben1[i];
    }
    if (threadIdx.x < 3) sb2[threadIdx.x] = ben2[threadIdx.x];
    __syncthreads();

    int e = blockIdx.x * blockDim.x + threadIdx.x;
    if (e >= E) return;
    int src = ei[e];
    int dst = ei[(size_t)E + e];

    // aggregate dis[src]*x2[src] into agg2[dst]
    {
        const float4* Y = &g_y[(size_t)src*4];
        float4 y0 = Y[0], y1 = Y[1], y2 = Y[2], y3 = Y[3];
        float* a = agg2 + (size_t)dst * 16;
        atomicAdd(a+ 0, y0.x); atomicAdd(a+ 1, y0.y); atomicAdd(a+ 2, y0.z); atomicAdd(a+ 3, y0.w);
        atomicAdd(a+ 4, y1.x); atomicAdd(a+ 5, y1.y); atomicAdd(a+ 6, y1.z); atomicAdd(a+ 7, y1.w);
        atomicAdd(a+ 8, y2.x); atomicAdd(a+ 9, y2.y); atomicAdd(a+10, y2.z); atomicAdd(a+11, y2.w);
        atomicAdd(a+12, y3.x); atomicAdd(a+13, y3.y); atomicAdd(a+14, y3.z); atomicAdd(a+15, y3.w);
    }

    // e1 = relu(A1[src] + ea@w_mid1 + B1[dst] + b_e1)
    float ea0 = ea[(size_t)e*3], ea1 = ea[(size_t)e*3+1], ea2 = ea[(size_t)e*3+2];
    float e1v[16];
    {
        const float4* A = &g_A1[(size_t)src*4];
        const float4* B = &g_B1[(size_t)dst*4];
        float av[16], bv[16];
#pragma unroll
        for (int q = 0; q < 4; q++) {
            float4 ta = A[q], tb = B[q];
            av[4*q]=ta.x; av[4*q+1]=ta.y; av[4*q+2]=ta.z; av[4*q+3]=ta.w;
            bv[4*q]=tb.x; bv[4*q+1]=tb.y; bv[4*q+2]=tb.z; bv[4*q+3]=tb.w;
        }
#pragma unroll
        for (int k = 0; k < 16; k++)
            e1v[k] = relu(av[k] + bv[k] + sbe1[k]
                          + ea0*sm1[k] + ea1*sm1[16+k] + ea2*sm1[32+k]);
    }

    // e2 = relu(A2[src] + e1@w_mid2 + B2[dst] + b_e2)
    float e2v[16];
    {
        const float4* A = &g_A2[(size_t)src*4];
        const float4* B = &g_B2[(size_t)dst*4];
#pragma unroll
        for (int q = 0; q < 4; q++) {
            float4 ta = A[q], tb = B[q];
            e2v[4*q  ] = ta.x + tb.x + sbe2[4*q  ];
            e2v[4*q+1] = ta.y + tb.y + sbe2[4*q+1];
            e2v[4*q+2] = ta.z + tb.z + sbe2[4*q+2];
            e2v[4*q+3] = ta.w + tb.w + sbe2[4*q+3];
        }
#pragma unroll
        for (int j = 0; j < 16; j++)
#pragma unroll
            for (int k = 0; k < 16; k++)
                e2v[k] += e1v[j] * sm2[j*16+k];
#pragma unroll
        for (int k = 0; k < 16; k++) e2v[k] = relu(e2v[k]);
    }

    // edge MLP: relu(e2@wen1+b) @ wen2 + b
    float t[16];
#pragma unroll
    for (int k = 0; k < 16; k++) t[k] = sb1[k];
#pragma unroll
    for (int j = 0; j < 16; j++)
#pragma unroll
        for (int k = 0; k < 16; k++) t[k] += e2v[j] * sw1[j*16+k];
    float o0 = sb2[0], o1 = sb2[1], o2 = sb2[2];
#pragma unroll
    for (int j = 0; j < 16; j++) {
        float tj = relu(t[j]);
        o0 += tj * sw2[j*3    ];
        o1 += tj * sw2[j*3 + 1];
        o2 += tj * sw2[j*3 + 2];
    }
    out_edge[(size_t)e*3    ] = o0;
    out_edge[(size_t)e*3 + 1] = o1;
    out_edge[(size_t)e*3 + 2] = o2;
}

// ----------------------------------------------------------- node MLP out
__global__ void k_node3(const float* __restrict__ wnn1, const float* __restrict__ bnn1,
                        const float* __restrict__ wnn2, const float* __restrict__ bnn2,
                        float* __restrict__ out_node, int N) {
    __shared__ float sw1[256], sb1[16], sw2[48], sb2[3];
    for (int i = threadIdx.x; i < 256; i += blockDim.x) sw1[i] = wnn1[i];
    for (int i = threadIdx.x; i < 48;  i += blockDim.x) sw2[i] = wnn2[i];
    for (int i = threadIdx.x; i < 16;  i += blockDim.x) sb1[i] = bnn1[i];
    if (threadIdx.x < 3) sb2[threadIdx.x] = bnn2[threadIdx.x];
    __syncthreads();
    int n = blockIdx.x * blockDim.x + threadIdx.x;
    if (n >= N) return;

    float dis = g_dis[n];
    const float* agg = g_agg2 + (size_t)n * 16;
    float h[16];
#pragma unroll
    for (int k = 0; k < 16; k++) h[k] = relu(dis * agg[k]);

    float t[16];
#pragma unroll
    for (int k = 0; k < 16; k++) t[k] = sb1[k];
#pragma unroll
    for (int j = 0; j < 16; j++)
#pragma unroll
        for (int k = 0; k < 16; k++) t[k] += h[j] * sw1[j*16+k];

    float o0 = sb2[0], o1 = sb2[1], o2 = sb2[2];
#pragma unroll
    for (int j = 0; j < 16; j++) {
        float tj = relu(t[j]);
        o0 += tj * sw2[j*3    ];
        o1 += tj * sw2[j*3 + 1];
        o2 += tj * sw2[j*3 + 2];
    }
    out_node[(size_t)n*3    ] = o0;
    out_node[(size_t)n*3 + 1] = o1;
    out_node[(size_t)n*3 + 2] = o2;
}

extern "C" void kernel_launch(void* const* d_in, const int* in_sizes, int n_in,
                              void* d_out, int out_size) {
    const float* x    = (const float*)d_in[0];
    const float* ea   = (const float*)d_in[1];
    const int*   ei   = (const int*)d_in[2];      // int32! (JAX x64 disabled)
    const float *wn1 = (const float*)d_in[3],  *bn1 = (const float*)d_in[4];
    const float *we1 = (const float*)d_in[5],  *be1 = (const float*)d_in[6];
    const float *wn2 = (const float*)d_in[7],  *bn2 = (const float*)d_in[8];
    const float *we2 = (const float*)d_in[9],  *be2 = (const float*)d_in[10];
    const float *wnn1= (const float*)d_in[11], *bnn1= (const float*)d_in[12];
    const float *wnn2= (const float*)d_in[13], *bnn2= (const float*)d_in[14];
    const float *wen1= (const float*)d_in[15], *ben1= (const float*)d_in[16];
    const float *wen2= (const float*)d_in[17], *ben2= (const float*)d_in[18];

    int N = in_sizes[0] / 3;
    int E = in_sizes[1] / 3;
    float* out_node = (float*)d_out;
    float* out_edge = out_node + (size_t)N * 3;

    void *pdeg, *pagg1, *pagg2;
    cudaGetSymbolAddress(&pdeg,  g_deg);
    cudaGetSymbolAddress(&pagg1, g_agg1);
    cudaGetSymbolAddress(&pagg2, g_agg2);
    cudaMemsetAsync(pdeg,  0, (size_t)N * sizeof(float));
    cudaMemsetAsync(pagg1, 0, (size_t)N * 16 * sizeof(float));
    cudaMemsetAsync(pagg2, 0, (size_t)N * 16 * sizeof(float));

    const int TB = 256;
    int gbE = (E + TB - 1) / TB;
    int gbN = (N + TB - 1) / TB;

    k_deg  <<<gbE, TB>>>(ei, E);
    k_node1<<<gbN, TB>>>(x, wn1, bn1, we1, N);
    k_agg  <<<gbE, TB>>>(ei, E, (float*)pagg1);
    k_node2<<<gbN, TB>>>(wn2, bn2, we2, N);
    k_edge2<<<gbE, TB>>>(ei, ea, we1, be1, we2, be2, wen1, ben1, wen2, ben2,
                         out_edge, (float*)pagg2, E);
    k_node3<<<gbN, TB>>>(wnn1, bnn1, wnn2, bnn2, out_node, N);
}

// round 3
// speedup vs baseline: 1.2139x; 1.2139x over previous
#include <cuda_runtime.h>

#define NMAX 100000
#define EMAX 3200000

// N-sized scratch (all __device__ globals; no allocation anywhere)
__device__ int    g_degi  [NMAX];
__device__ int    g_rowptr[NMAX + 1];
__device__ int    g_next  [NMAX];
__device__ int    g_ssrc  [EMAX];     // src ids sorted by dst (CSR adjacency)
__device__ float  g_dis   [NMAX];
__device__ float4 g_y     [NMAX * 4]; // dis[n] * (lin_node output), layer 1 then layer 2
__device__ float4 g_A1    [NMAX * 4]; // x1 @ w_e1[0:16]
__device__ float4 g_B1    [NMAX * 4]; // x1 @ w_e1[19:35]
__device__ float4 g_A2    [NMAX * 4]; // x2 @ w_e2[0:16]
__device__ float4 g_B2    [NMAX * 4]; // x2 @ w_e2[32:48]
__device__ float  g_agg1  [NMAX * 16];
__device__ float  g_agg2  [NMAX * 16];

__device__ __forceinline__ float relu(float v) { return fmaxf(v, 0.0f); }

// ---------------------------------------------------------------- degree
__global__ void k_deg(const int* __restrict__ ei, int E) {
    int e = blockIdx.x * blockDim.x + threadIdx.x;
    if (e < E) atomicAdd(&g_degi[ei[(size_t)E + e]], 1);
}

// ------------------------------------------ exclusive scan (single block)
__global__ void k_scan(int N, int E) {
    __shared__ int ssum[1024];
    int t = threadIdx.x;
    int CH = (N + 1023) >> 10;
    int base = t * CH;
    int end  = min(base + CH, N);
    int s = 0;
    for (int i = base; i < end; i++) s += g_degi[i];
    ssum[t] = s;
    __syncthreads();
    // Hillis-Steele inclusive scan
    for (int off = 1; off < 1024; off <<= 1) {
        int u = (t >= off) ? ssum[t - off] : 0;
        __syncthreads();
        ssum[t] += u;
        __syncthreads();
    }
    int running = ssum[t] - s;   // exclusive prefix of this thread's chunk
    for (int i = base; i < end; i++) {
        g_rowptr[i] = running;
        g_next[i]   = running;
        running += g_degi[i];
    }
    if (t == 0) g_rowptr[N] = E;
}

// ----------------------------------------------------- scatter into CSR
__global__ void k_scatter(const int* __restrict__ ei, int E) {
    int e = blockIdx.x * blockDim.x + threadIdx.x;
    if (e >= E) return;
    int src = ei[e];
    int dst = ei[(size_t)E + e];
    int pos = atomicAdd(&g_next[dst], 1);
    g_ssrc[pos] = src;
}

// ------------------------------------------------- node precompute layer 1
__global__ void k_node1(const float* __restrict__ x,
                        const float* __restrict__ wn1, const float* __restrict__ bn1,
                        const float* __restrict__ we1, int N) {
    __shared__ float swn[48], sbn[16], sA[256], sB[256];
    for (int i = threadIdx.x; i < 48; i += blockDim.x) swn[i] = wn1[i];
    for (int i = threadIdx.x; i < 16; i += blockDim.x) sbn[i] = bn1[i];
    for (int i = threadIdx.x; i < 256; i += blockDim.x) {
        sA[i] = we1[i];            // rows 0..15  (x_src part)
        sB[i] = we1[304 + i];      // rows 19..34 (x_dst part)
    }
    __syncthreads();
    int n = blockIdx.x * blockDim.x + threadIdx.x;
    if (n >= N) return;

    float x0 = x[(size_t)n*3], x1 = x[(size_t)n*3+1], x2 = x[(size_t)n*3+2];
    float dis = rsqrtf((float)g_degi[n]);
    g_dis[n] = dis;

    float h[16];
#pragma unroll
    for (int k = 0; k < 16; k++)
        h[k] = sbn[k] + x0*swn[k] + x1*swn[16+k] + x2*swn[32+k];

    float4* Y = &g_y[(size_t)n*4];
#pragma unroll
    for (int q = 0; q < 4; q++)
        Y[q] = make_float4(dis*h[4*q], dis*h[4*q+1], dis*h[4*q+2], dis*h[4*q+3]);

    float a[16], b[16];
#pragma unroll
    for (int k = 0; k < 16; k++) { a[k] = 0.f; b[k] = 0.f; }
#pragma unroll
    for (int j = 0; j < 16; j++)
#pragma unroll
        for (int k = 0; k < 16; k++) {
            a[k] += h[j] * sA[j*16+k];
            b[k] += h[j] * sB[j*16+k];
        }
    float4* A = &g_A1[(size_t)n*4];
    float4* B = &g_B1[(size_t)n*4];
#pragma unroll
    for (int q = 0; q < 4; q++) {
        A[q] = make_float4(a[4*q], a[4*q+1], a[4*q+2], a[4*q+3]);
        B[q] = make_float4(b[4*q], b[4*q+1], b[4*q+2], b[4*q+3]);
    }
}

// ------------------------- CSR gather aggregation: agg[n] = sum y[src(e)]
__global__ void k_aggc(float* __restrict__ agg, int N) {
    int n = blockIdx.x * blockDim.x + threadIdx.x;
    if (n >= N) return;
    int s = g_rowptr[n];
    int e = g_rowptr[n + 1];
    float a0=0,a1=0,a2=0,a3=0,a4=0,a5=0,a6=0,a7=0;
    float a8=0,a9=0,a10=0,a11=0,a12=0,a13=0,a14=0,a15=0;
    for (int p = s; p < e; p++) {
        int src = g_ssrc[p];
        const float4* Y = &g_y[(size_t)src*4];
        float4 v0 = Y[0], v1 = Y[1], v2 = Y[2], v3 = Y[3];
        a0+=v0.x; a1+=v0.y; a2+=v0.z; a3+=v0.w;
        a4+=v1.x; a5+=v1.y; a6+=v1.z; a7+=v1.w;
        a8+=v2.x; a9+=v2.y; a10+=v2.z; a11+=v2.w;
        a12+=v3.x; a13+=v3.y; a14+=v3.z; a15+=v3.w;
    }
    float4* A = (float4*)(agg + (size_t)n * 16);
    A[0] = make_float4(a0,a1,a2,a3);
    A[1] = make_float4(a4,a5,a6,a7);
    A[2] = make_float4(a8,a9,a10,a11);
    A[3] = make_float4(a12,a13,a14,a15);
}

// ------------------------------------------------- node precompute layer 2
__global__ void k_node2(const float* __restrict__ wn2, const float* __restrict__ bn2,
                        const float* __restrict__ we2, int N) {
    __shared__ float sw[256], sbn[16], sA[256], sB[256];
    for (int i = threadIdx.x; i < 16; i += blockDim.x) sbn[i] = bn2[i];
    for (int i = threadIdx.x; i < 256; i += blockDim.x) {
        sw[i] = wn2[i];
        sA[i] = we2[i];            // rows 0..15
        sB[i] = we2[512 + i];      // rows 32..47
    }
    __syncthreads();
    int n = blockIdx.x * blockDim.x + threadIdx.x;
    if (n >= N) return;

    float dis = g_dis[n];
    const float* agg = g_agg1 + (size_t)n * 16;
    float h[16];
#pragma unroll
    for (int k = 0; k < 16; k++) h[k] = relu(dis * agg[k]);

    float v[16];
#pragma unroll
    for (int k = 0; k < 16; k++) v[k] = sbn[k];
#pragma unroll
    for (int j = 0; j < 16; j++)
#pragma unroll
        for (int k = 0; k < 16; k++) v[k] += h[j] * sw[j*16+k];

    float4* Y = &g_y[(size_t)n*4];
#pragma unroll
    for (int q = 0; q < 4; q++)
        Y[q] = make_float4(dis*v[4*q], dis*v[4*q+1], dis*v[4*q+2], dis*v[4*q+3]);

    float a[16], b[16];
#pragma unroll
    for (int k = 0; k < 16; k++) { a[k] = 0.f; b[k] = 0.f; }
#pragma unroll
    for (int j = 0; j < 16; j++)
#pragma unroll
        for (int k = 0; k < 16; k++) {
            a[k] += v[j] * sA[j*16+k];
            b[k] += v[j] * sB[j*16+k];
        }
    float4* A = &g_A2[(size_t)n*4];
    float4* B = &g_B2[(size_t)n*4];
#pragma unroll
    for (int q = 0; q < 4; q++) {
        A[q] = make_float4(a[4*q], a[4*q+1], a[4*q+2], a[4*q+3]);
        B[q] = make_float4(b[4*q], b[4*q+1], b[4*q+2], b[4*q+3]);
    }
}

// ------- layer-2 edge kernel: recompute e1, compute e2, edge MLP
__global__ void k_edge2(const int* __restrict__ ei, const float* __restrict__ ea,
                        const float* __restrict__ we1, const float* __restrict__ be1,
                        const float* __restrict__ we2, const float* __restrict__ be2,
                        const float* __restrict__ wen1, const float* __restrict__ ben1,
                        const float* __restrict__ wen2, const float* __restrict__ ben2,
                        float* __restrict__ out_edge, int E) {
    __shared__ float sm1[48], sbe1[16], sm2[256], sbe2[16], sw1[256], sb1[16], sw2[48], sb2[3];
    for (int i = threadIdx.x; i < 48; i += blockDim.x) {
        sm1[i] = we1[256 + i];     // w_e1 rows 16..18 (edge_attr part)
        sw2[i] = wen2[i];
    }
    for (int i = threadIdx.x; i < 256; i += blockDim.x) {
        sm2[i] = we2[256 + i];     // w_e2 rows 16..31 (edge part)
        sw1[i] = wen1[i];
    }
    for (int i = threadIdx.x; i < 16; i += blockDim.x) {
        sbe1[i] = be1[i]; sbe2[i] = be2[i]; sb1[i] = ben1[i];
    }
    if (threadIdx.x < 3) sb2[threadIdx.x] = ben2[threadIdx.x];
    __syncthreads();

    int e = blockIdx.x * blockDim.x + threadIdx.x;
    if (e >= E) return;
    int src = ei[e];
    int dst = ei[(size_t)E + e];

    // e1 = relu(A1[src] + ea@w_mid1 + B1[dst] + b_e1)
    float ea0 = ea[(size_t)e*3], ea1 = ea[(size_t)e*3+1], ea2 = ea[(size_t)e*3+2];
    float e1v[16];
    {
        const float4* A = &g_A1[(size_t)src*4];
        const float4* B = &g_B1[(size_t)dst*4];
        float av[16], bv[16];
#pragma unroll
        for (int q = 0; q < 4; q++) {
            float4 ta = A[q], tb = B[q];
            av[4*q]=ta.x; av[4*q+1]=ta.y; av[4*q+2]=ta.z; av[4*q+3]=ta.w;
            bv[4*q]=tb.x; bv[4*q+1]=tb.y; bv[4*q+2]=tb.z; bv[4*q+3]=tb.w;
        }
#pragma unroll
        for (int k = 0; k < 16; k++)
            e1v[k] = relu(av[k] + bv[k] + sbe1[k]
                          + ea0*sm1[k] + ea1*sm1[16+k] + ea2*sm1[32+k]);
    }

    // e2 = relu(A2[src] + e1@w_mid2 + B2[dst] + b_e2)
    float e2v[16];
    {
        const float4* A = &g_A2[(size_t)src*4];
        const float4* B = &g_B2[(size_t)dst*4];
#pragma unroll
        for (int q = 0; q < 4; q++) {
            float4 ta = A[q], tb = B[q];
            e2v[4*q  ] = ta.x + tb.x + sbe2[4*q  ];
            e2v[4*q+1] = ta.y + tb.y + sbe2[4*q+1];
            e2v[4*q+2] = ta.z + tb.z + sbe2[4*q+2];
            e2v[4*q+3] = ta.w + tb.w + sbe2[4*q+3];
        }
#pragma unroll
        for (int j = 0; j < 16; j++)
#pragma unroll
            for (int k = 0; k < 16; k++)
                e2v[k] += e1v[j] * sm2[j*16+k];
#pragma unroll
        for (int k = 0; k < 16; k++) e2v[k] = relu(e2v[k]);
    }

    // edge MLP: relu(e2@wen1+b) @ wen2 + b
    float t[16];
#pragma unroll
    for (int k = 0; k < 16; k++) t[k] = sb1[k];
#pragma unroll
    for (int j = 0; j < 16; j++)
#pragma unroll
        for (int k = 0; k < 16; k++) t[k] += e2v[j] * sw1[j*16+k];
    float o0 = sb2[0], o1 = sb2[1], o2 = sb2[2];
#pragma unroll
    for (int j = 0; j < 16; j++) {
        float tj = relu(t[j]);
        o0 += tj * sw2[j*3    ];
        o1 += tj * sw2[j*3 + 1];
        o2 += tj * sw2[j*3 + 2];
    }
    out_edge[(size_t)e*3    ] = o0;
    out_edge[(size_t)e*3 + 1] = o1;
    out_edge[(size_t)e*3 + 2] = o2;
}

// ----------------------------------------------------------- node MLP out
__global__ void k_node3(const float* __restrict__ wnn1, const float* __restrict__ bnn1,
                        const float* __restrict__ wnn2, const float* __restrict__ bnn2,
                        float* __restrict__ out_node, int N) {
    __shared__ float sw1[256], sb1[16], sw2[48], sb2[3];
    for (int i = threadIdx.x; i < 256; i += blockDim.x) sw1[i] = wnn1[i];
    for (int i = threadIdx.x; i < 48;  i += blockDim.x) sw2[i] = wnn2[i];
    for (int i = threadIdx.x; i < 16;  i += blockDim.x) sb1[i] = bnn1[i];
    if (threadIdx.x < 3) sb2[threadIdx.x] = bnn2[threadIdx.x];
    __syncthreads();
    int n = blockIdx.x * blockDim.x + threadIdx.x;
    if (n >= N) return;

    float dis = g_dis[n];
    const float* agg = g_agg2 + (size_t)n * 16;
    float h[16];
#pragma unroll
    for (int k = 0; k < 16; k++) h[k] = relu(dis * agg[k]);

    float t[16];
#pragma unroll
    for (int k = 0; k < 16; k++) t[k] = sb1[k];
#pragma unroll
    for (int j = 0; j < 16; j++)
#pragma unroll
        for (int k = 0; k < 16; k++) t[k] += h[j] * sw1[j*16+k];

    float o0 = sb2[0], o1 = sb2[1], o2 = sb2[2];
#pragma unroll
    for (int j = 0; j < 16; j++) {
        float tj = relu(t[j]);
        o0 += tj * sw2[j*3    ];
        o1 += tj * sw2[j*3 + 1];
        o2 += tj * sw2[j*3 + 2];
    }
    out_node[(size_t)n*3    ] = o0;
    out_node[(size_t)n*3 + 1] = o1;
    out_node[(size_t)n*3 + 2] = o2;
}

extern "C" void kernel_launch(void* const* d_in, const int* in_sizes, int n_in,
                              void* d_out, int out_size) {
    const float* x    = (const float*)d_in[0];
    const float* ea   = (const float*)d_in[1];
    const int*   ei   = (const int*)d_in[2];      // int32 (JAX x64 disabled)
    const float *wn1 = (const float*)d_in[3],  *bn1 = (const float*)d_in[4];
    const float *we1 = (const float*)d_in[5],  *be1 = (const float*)d_in[6];
    const float *wn2 = (const float*)d_in[7],  *bn2 = (const float*)d_in[8];
    const float *we2 = (const float*)d_in[9],  *be2 = (const float*)d_in[10];
    const float *wnn1= (const float*)d_in[11], *bnn1= (const float*)d_in[12];
    const float *wnn2= (const float*)d_in[13], *bnn2= (const float*)d_in[14];
    const float *wen1= (const float*)d_in[15], *ben1= (const float*)d_in[16];
    const float *wen2= (const float*)d_in[17], *ben2= (const float*)d_in[18];

    int N = in_sizes[0] / 3;
    int E = in_sizes[1] / 3;
    float* out_node = (float*)d_out;
    float* out_edge = out_node + (size_t)N * 3;

    void *pdegi, *pagg1, *pagg2;
    cudaGetSymbolAddress(&pdegi, g_degi);
    cudaGetSymbolAddress(&pagg1, g_agg1);
    cudaGetSymbolAddress(&pagg2, g_agg2);
    cudaMemsetAsync(pdegi, 0, (size_t)N * sizeof(int));

    const int TB = 256;
    int gbE = (E + TB - 1) / TB;
    int gbN = (N + TB - 1) / TB;

    k_deg    <<<gbE, TB>>>(ei, E);
    k_scan   <<<1, 1024>>>(N, E);
    k_scatter<<<gbE, TB>>>(ei, E);
    k_node1  <<<gbN, TB>>>(x, wn1, bn1, we1, N);
    k_aggc   <<<gbN, TB>>>((float*)pagg1, N);
    k_node2  <<<gbN, TB>>>(wn2, bn2, we2, N);
    k_edge2  <<<gbE, TB>>>(ei, ea, we1, be1, we2, be2, wen1, ben1, wen2, ben2,
                           out_edge, E);
    k_aggc   <<<gbN, TB>>>((float*)pagg2, N);
    k_node3  <<<gbN, TB>>>(wnn1, bnn1, wnn2, bnn2, out_node, N);
}